// round 3
// baseline (speedup 1.0000x reference)
#include <cuda_runtime.h>
#include <cstdint>

// Problem constants
#define Bb 32
#define Cc 64
#define Lc 8192
#define Mm (Bb * Lc)            // 262144 columns
#define NBLK 512                // gram/apply blocks (each handles 512 columns)
#define EPSV 1e-5f

// ---------------- scratch (device globals; no allocation allowed) ----------------
__device__ __align__(16) float g_gram_part[NBLK * 4096];   // 8 MB partial Grams
__device__ __align__(16) float g_sum_part[NBLK * 64];
__device__ __align__(16) float g_gram[4096];
__device__ __align__(16) float g_mean[64];
__device__ __align__(16) float g_wmT[4096];                // wmT[cp][c] = wm[c][cp]
__device__ __align__(16) float g_bias[64];                 // wm @ mean

// ---------------- f32x2 helpers (FFMA2: 2x fp32 FMA throughput) ----------------
__device__ __forceinline__ unsigned long long dup2(float v) {
    unsigned long long r;
    asm("mov.b64 %0, {%1, %1};" : "=l"(r) : "f"(v));
    return r;
}
__device__ __forceinline__ void fma2(unsigned long long& d, unsigned long long a,
                                     unsigned long long b) {
    asm("fma.rn.f32x2 %0, %1, %2, %0;" : "+l"(d) : "l"(a), "l"(b));
}
__device__ __forceinline__ float2 unpk(unsigned long long v) {
    float2 r;
    asm("mov.b64 {%0, %1}, %2;" : "=f"(r.x), "=f"(r.y) : "l"(v));
    return r;
}

// ================= Kernel 1: per-block partial Gram + channel sums =================
// Grid 512: block = (batch b, 512-column chunk). 8 inner tiles of 64 columns.
// Tile stored transposed in smem as sT[k][c] (row stride 68) so both MMA operands
// are contiguous vector loads.
__global__ __launch_bounds__(256) void gram_kernel(const float* __restrict__ X) {
    __shared__ __align__(16) float sT[64 * 68];
    const int tid = threadIdx.x;
    const int bid = blockIdx.x;
    const int b  = bid >> 4;
    const int l0 = (bid & 15) << 9;                 // 512 columns per block
    const float* Xb = X + (size_t)b * Cc * Lc;

    const int ty = tid >> 4, tx = tid & 15;
    const int r  = ty * 4;                          // output rows   (channel c1)
    const int cc = tx * 4;                          // output cols   (channel c2)

    unsigned long long acc[4][2] = {};
    float csum = 0.f;

    for (int t = 0; t < 8; t++) {
        const int l = l0 + t * 64;
        // load 64c x 64k tile, transposed into sT[k][c]
        #pragma unroll
        for (int it = 0; it < 4; it++) {
            int p = it * 256 + tid;
            int c = p >> 4, k4 = p & 15;
            float4 v = *(const float4*)&Xb[c * Lc + l + k4 * 4];
            int kb = k4 * 4;
            sT[(kb + 0) * 68 + c] = v.x;
            sT[(kb + 1) * 68 + c] = v.y;
            sT[(kb + 2) * 68 + c] = v.z;
            sT[(kb + 3) * 68 + c] = v.w;
        }
        __syncthreads();

        // channel sums (threads 0..63, conflict-free consecutive reads)
        if (tid < 64) {
            #pragma unroll 16
            for (int k = 0; k < 64; k++) csum += sT[k * 68 + tid];
        }

        // rank-64 update of the 64x64 Gram, FFMA2 inner loop
        #pragma unroll 8
        for (int k = 0; k < 64; k++) {
            float4 a4 = *(const float4*)&sT[k * 68 + r];
            ulonglong2 b2 = *(const ulonglong2*)&sT[k * 68 + cc];
            unsigned long long a;
            a = dup2(a4.x); fma2(acc[0][0], a, b2.x); fma2(acc[0][1], a, b2.y);
            a = dup2(a4.y); fma2(acc[1][0], a, b2.x); fma2(acc[1][1], a, b2.y);
            a = dup2(a4.z); fma2(acc[2][0], a, b2.x); fma2(acc[2][1], a, b2.y);
            a = dup2(a4.w); fma2(acc[3][0], a, b2.x); fma2(acc[3][1], a, b2.y);
        }
        __syncthreads();
    }

    float* gp = g_gram_part + (size_t)bid * 4096;
    #pragma unroll
    for (int i = 0; i < 4; i++) {
        float2 p0 = unpk(acc[i][0]), p1 = unpk(acc[i][1]);
        *(float4*)&gp[(r + i) * 64 + cc] = make_float4(p0.x, p0.y, p1.x, p1.y);
    }
    if (tid < 64) g_sum_part[bid * 64 + tid] = csum;
}

// ================= Kernel 2: deterministic reduction of partials =================
__global__ void reduce_kernel() {
    const int tid = threadIdx.x;
    if (blockIdx.x < 16) {
        const int e = blockIdx.x * 256 + tid;
        float a0 = 0.f, a1 = 0.f, a2 = 0.f, a3 = 0.f;
        for (int p = 0; p < NBLK; p += 4) {
            a0 += g_gram_part[(size_t)(p + 0) * 4096 + e];
            a1 += g_gram_part[(size_t)(p + 1) * 4096 + e];
            a2 += g_gram_part[(size_t)(p + 2) * 4096 + e];
            a3 += g_gram_part[(size_t)(p + 3) * 4096 + e];
        }
        g_gram[e] = (a0 + a1) + (a2 + a3);
    } else if (tid < 64) {
        float a0 = 0.f, a1 = 0.f, a2 = 0.f, a3 = 0.f;
        for (int p = 0; p < NBLK; p += 4) {
            a0 += g_sum_part[(p + 0) * 64 + tid];
            a1 += g_sum_part[(p + 1) * 64 + tid];
            a2 += g_sum_part[(p + 2) * 64 + tid];
            a3 += g_sum_part[(p + 3) * 64 + tid];
        }
        g_mean[tid] = ((a0 + a1) + (a2 + a3)) * (1.0f / (float)Mm);
    }
}

// ================= Kernel 3: Sigma + Newton-Schulz (single block) =================
__device__ __align__(16) float dummy_keep;  // (nothing)

__device__ __forceinline__ void mm64(const float* A, const float* Bm, float* Cm, int tid) {
    const int ty = tid >> 4, tx = tid & 15;
    const int r = ty * 4, cb = tx * 4;
    unsigned long long acc[4][2] = {};
    #pragma unroll 8
    for (int k = 0; k < 64; k++) {
        ulonglong2 b2 = *(const ulonglong2*)&Bm[k * 64 + cb];
        #pragma unroll
        for (int i = 0; i < 4; i++) {
            unsigned long long a = dup2(A[(r + i) * 64 + k]);
            fma2(acc[i][0], a, b2.x);
            fma2(acc[i][1], a, b2.y);
        }
    }
    __syncthreads();   // all reads done before any write (C may alias A/B)
    #pragma unroll
    for (int i = 0; i < 4; i++) {
        float2 p0 = unpk(acc[i][0]), p1 = unpk(acc[i][1]);
        *(float4*)&Cm[(r + i) * 64 + cb] = make_float4(p0.x, p0.y, p1.x, p1.y);
    }
    __syncthreads();
}

__global__ __launch_bounds__(256) void solver_kernel() {
    __shared__ __align__(16) float P[4096];
    __shared__ __align__(16) float S[4096];
    __shared__ __align__(16) float T1[4096];
    const int tid = threadIdx.x;
    const float inv_m = 1.0f / (float)Mm;

    // Sigma = eps*I + G/m - mean*mean^T
    for (int e = tid; e < 4096; e += 256) {
        int c1 = e >> 6, c2 = e & 63;
        S[e] = g_gram[e] * inv_m - g_mean[c1] * g_mean[c2] + ((c1 == c2) ? EPSV : 0.0f);
    }
    __syncthreads();

    // every thread computes the trace (broadcast reads; bitwise identical)
    float tr = 0.f;
    #pragma unroll
    for (int c = 0; c < 64; c++) tr += S[c * 65];
    const float rTr = 1.0f / tr;
    __syncthreads();

    for (int e = tid; e < 4096; e += 256) {
        S[e] *= rTr;
        int c1 = e >> 6, c2 = e & 63;
        P[e] = (c1 == c2) ? 1.0f : 0.0f;
    }
    __syncthreads();

    // 5 Newton-Schulz iterations: P = 1.5P - 0.5*(P@P@P)@S
    for (int it = 0; it < 5; it++) {
        mm64(P, P, T1, tid);   // T1 = P^2
        mm64(T1, P, T1, tid);  // T1 = P^3
        mm64(T1, S, T1, tid);  // T1 = P^3 @ SigmaN
        for (int e = tid; e < 4096; e += 256)
            P[e] = 1.5f * P[e] - 0.5f * T1[e];
        __syncthreads();
    }

    const float sq = sqrtf(rTr);
    // store wm transposed for the apply kernel, and bias = wm @ mean
    for (int e = tid; e < 4096; e += 256) {
        int c = e >> 6, cp = e & 63;
        g_wmT[cp * 64 + c] = P[e] * sq;
    }
    if (tid < 64) {
        float bsum = 0.f;
        #pragma unroll 8
        for (int cp = 0; cp < 64; cp++) bsum += P[tid * 64 + cp] * g_mean[cp];
        g_bias[tid] = bsum * sq;
    }
}

// ================= Kernel 4: apply  Y = wm @ X - bias =================
__global__ __launch_bounds__(256) void apply_kernel(const float* __restrict__ X,
                                                    float* __restrict__ Y) {
    __shared__ __align__(16) float s_w[4096];   // wmT[cp][c]
    __shared__ __align__(16) float s_x[4096];   // x tile [cp][j]
    __shared__ float s_b[64];
    const int tid = threadIdx.x;

    for (int e = tid; e < 4096; e += 256) s_w[e] = g_wmT[e];
    if (tid < 64) s_b[tid] = g_bias[tid];

    const int bid = blockIdx.x;
    const int b  = bid >> 4;
    const int l0 = (bid & 15) << 9;
    const float* Xb = X + (size_t)b * Cc * Lc;
    float* Yb = Y + (size_t)b * Cc * Lc;

    const int ty = tid >> 4, tx = tid & 15;
    const int r = ty * 4, jj = tx * 4;
    __syncthreads();

    for (int t = 0; t < 8; t++) {
        const int l = l0 + t * 64;
        #pragma unroll
        for (int it = 0; it < 4; it++) {
            int p = it * 256 + tid;
            int c = p >> 4, k4 = p & 15;
            *(float4*)&s_x[c * 64 + k4 * 4] = *(const float4*)&Xb[c * Lc + l + k4 * 4];
        }
        __syncthreads();

        unsigned long long acc[4][2] = {};
        #pragma unroll 8
        for (int k = 0; k < 64; k++) {
            float4 a4 = *(const float4*)&s_w[k * 64 + r];
            ulonglong2 b2 = *(const ulonglong2*)&s_x[k * 64 + jj];
            unsigned long long a;
            a = dup2(a4.x); fma2(acc[0][0], a, b2.x); fma2(acc[0][1], a, b2.y);
            a = dup2(a4.y); fma2(acc[1][0], a, b2.x); fma2(acc[1][1], a, b2.y);
            a = dup2(a4.z); fma2(acc[2][0], a, b2.x); fma2(acc[2][1], a, b2.y);
            a = dup2(a4.w); fma2(acc[3][0], a, b2.x); fma2(acc[3][1], a, b2.y);
        }

        #pragma unroll
        for (int i = 0; i < 4; i++) {
            float bb = s_b[r + i];
            float2 p0 = unpk(acc[i][0]), p1 = unpk(acc[i][1]);
            *(float4*)&Yb[(r + i) * Lc + l + jj] =
                make_float4(p0.x - bb, p0.y - bb, p1.x - bb, p1.y - bb);
        }
        __syncthreads();
    }
}

// ================= launch =================
extern "C" void kernel_launch(void* const* d_in, const int* in_sizes, int n_in,
                              void* d_out, int out_size) {
    const float* X = (const float*)d_in[0];
    float* Y = (float*)d_out;

    gram_kernel<<<NBLK, 256>>>(X);
    reduce_kernel<<<17, 256>>>();
    solver_kernel<<<1, 256>>>();
    apply_kernel<<<NBLK, 256>>>(X, Y);
}